// round 7
// baseline (speedup 1.0000x reference)
#include <cuda_runtime.h>
#include <math.h>

#define BB 4
#define SS 512
#define HH 768
#define DD 24
#define MM 96
#define RR (BB*SS)      // 2048
#define KX (3*HH)       // 2304
#define ZST 514         // padded transpose stride

typedef unsigned long long ull;

// ---------------- f32x2 packed helpers (pairwise kernel) ----------------
__device__ __forceinline__ ull pk2(float lo, float hi) {
    ull r; asm("mov.b64 %0, {%1, %2};" : "=l"(r) : "f"(lo), "f"(hi)); return r;
}
__device__ __forceinline__ ull dup2(float x) { return pk2(x, x); }
__device__ __forceinline__ void upk2(ull v, float& lo, float& hi) {
    asm("mov.b64 {%0, %1}, %2;" : "=f"(lo), "=f"(hi) : "l"(v));
}
__device__ __forceinline__ ull fma2(ull a, ull b, ull c) {
    ull d; asm("fma.rn.f32x2 %0, %1, %2, %3;" : "=l"(d) : "l"(a), "l"(b), "l"(c)); return d;
}
__device__ __forceinline__ ull abs2(ull a) { return a & 0x7fffffff7fffffffULL; }

// ---------------- tf32 helpers ----------------
__device__ __forceinline__ unsigned cvt_tf32(float x) {
    unsigned r; asm("cvt.rna.tf32.f32 %0, %1;" : "=r"(r) : "f"(x)); return r;
}
__device__ __forceinline__ void mma1688(float* c, const unsigned* a, const unsigned* b) {
    asm("mma.sync.aligned.m16n8k8.row.col.f32.tf32.tf32.f32 "
        "{%0,%1,%2,%3}, {%4,%5,%6,%7}, {%8,%9}, {%0,%1,%2,%3};"
        : "+f"(c[0]), "+f"(c[1]), "+f"(c[2]), "+f"(c[3])
        : "r"(a[0]), "r"(a[1]), "r"(a[2]), "r"(a[3]), "r"(b[0]), "r"(b[1]));
}

// ---------------- scratch ----------------
__device__ __align__(16) float g_Zj[BB*SS*DD];
__device__ __align__(16) float g_Zi[BB*SS*DD];
__device__ __align__(16) float g_probs[BB*SS*SS];
__device__ __align__(16) float g_ctx[BB*SS*HH];
__device__ __align__(16) float g_mhid[RR*HH];

// ---------------- K1: Z projections ----------------
__global__ void proj_kernel(const float* __restrict__ Hj, const float* __restrict__ Hi,
                            const float* __restrict__ Wpj, const float* __restrict__ Wpi)
{
    int which = blockIdx.y;
    const float* Hsrc = which ? Hi : Hj;
    const float* W    = which ? Wpi : Wpj;
    float* Z          = which ? g_Zi : g_Zj;
    int row = blockIdx.x * 8 + threadIdx.y;
    int col = threadIdx.x;
    const float* h = Hsrc + (size_t)row * HH;
    float acc = 0.f;
    #pragma unroll 8
    for (int k = 0; k < HH; ++k)
        acc = fmaf(h[k], W[k*DD + col], acc);
    Z[row*DD + col] = acc;
}

// ---------------- K2: fused pairwise scores + softmax -> probs (f32x2, fp32-exact) ----------------
__global__ void __launch_bounds__(256) pairwise_kernel(
        const float* __restrict__ Ws1, const float* __restrict__ bs1,
        const float* __restrict__ ws2, const float* __restrict__ bs2p,
        const int*   __restrict__ mask)
{
    extern __shared__ float smem[];
    float2* sPair  = (float2*)smem;
    float*  sZiT   = smem + 2*DD*MM;
    float*  sLog   = sZiT + DD*ZST;
    float*  sBias  = sLog + SS;
    float*  sZj    = sBias + MM;
    float*  sRed   = sZj + DD;

    int b = blockIdx.y, p = blockIdx.x;
    int tid = threadIdx.x;
    int lane = tid & 31, warp = tid >> 5;

    if (tid < DD) sZj[tid] = g_Zj[((size_t)b*SS + p)*DD + tid];
    __syncthreads();

    {
        const float4* src = (const float4*)(g_Zi + (size_t)b*SS*DD);
        for (int i = tid; i < SS*DD/4; i += 256) {
            float4 v = src[i];
            int q = (4*i) / DD, d0 = (4*i) % DD;
            sZiT[(d0+0)*ZST+q] = v.x;
            sZiT[(d0+1)*ZST+q] = v.y;
            sZiT[(d0+2)*ZST+q] = v.z;
            sZiT[(d0+3)*ZST+q] = v.w;
        }
    }
    for (int idx = tid; idx < DD*MM; idx += 256) {
        int d = idx / MM, m = idx - d*MM;
        float w1i = Ws1[(DD   + d)*MM + m];
        float w1h = Ws1[(2*DD + d)*MM + m];
        float w1d = Ws1[(3*DD + d)*MM + m];
        sPair[idx] = make_float2(fmaf(sZj[d], w1h, w1i), w1d);
    }
    if (tid < MM) {
        float acc = bs1[tid];
        #pragma unroll
        for (int d = 0; d < DD; ++d)
            acc = fmaf(sZj[d], Ws1[d*MM + tid], acc);
        sBias[tid] = acc;
    }
    __syncthreads();

    float zj[DD];
    #pragma unroll
    for (int d = 0; d < DD; ++d) zj[d] = sZj[d];

    int m0 = lane, m1 = lane + 32, m2 = lane + 64;
    float wsa = ws2[m0], wsb = ws2[m1], wsc = ws2[m2];
    ull bi0p = dup2(sBias[m0]), bi1p = dup2(sBias[m1]), bi2p = dup2(sBias[m2]);
    const ull NEG1 = dup2(-1.0f);
    float bsc = bs2p[0];
    const int* mrow = mask + b*SS;

    for (int it = 0; it < SS/64; ++it) {
        int qb = it*64 + warp*8;
        ull a00=bi0p,a01=bi1p,a02=bi2p, a10=bi0p,a11=bi1p,a12=bi2p;
        ull a20=bi0p,a21=bi1p,a22=bi2p, a30=bi0p,a31=bi1p,a32=bi2p;

        #pragma unroll
        for (int d = 0; d < DD; ++d) {
            const float2* zr = (const float2*)&sZiT[d*ZST + qb];
            float2 z01f = zr[0], z23f = zr[1], z45f = zr[2], z67f = zr[3];
            ull z01 = pk2(z01f.x, z01f.y);
            ull z23 = pk2(z23f.x, z23f.y);
            ull z45 = pk2(z45f.x, z45f.y);
            ull z67 = pk2(z67f.x, z67f.y);
            ull zjd = dup2(zj[d]);
            ull f01 = abs2(fma2(z01, NEG1, zjd));
            ull f23 = abs2(fma2(z23, NEG1, zjd));
            ull f45 = abs2(fma2(z45, NEG1, zjd));
            ull f67 = abs2(fma2(z67, NEG1, zjd));
            float2 w0 = sPair[d*MM + m0];
            float2 w1 = sPair[d*MM + m1];
            float2 w2 = sPair[d*MM + m2];
            ull wc0 = dup2(w0.x), wd0 = dup2(w0.y);
            ull wc1 = dup2(w1.x), wd1 = dup2(w1.y);
            ull wc2 = dup2(w2.x), wd2 = dup2(w2.y);
            a00 = fma2(z01, wc0, a00); a00 = fma2(f01, wd0, a00);
            a01 = fma2(z01, wc1, a01); a01 = fma2(f01, wd1, a01);
            a02 = fma2(z01, wc2, a02); a02 = fma2(f01, wd2, a02);
            a10 = fma2(z23, wc0, a10); a10 = fma2(f23, wd0, a10);
            a11 = fma2(z23, wc1, a11); a11 = fma2(f23, wd1, a11);
            a12 = fma2(z23, wc2, a12); a12 = fma2(f23, wd2, a12);
            a20 = fma2(z45, wc0, a20); a20 = fma2(f45, wd0, a20);
            a21 = fma2(z45, wc1, a21); a21 = fma2(f45, wd1, a21);
            a22 = fma2(z45, wc2, a22); a22 = fma2(f45, wd2, a22);
            a30 = fma2(z67, wc0, a30); a30 = fma2(f67, wd0, a30);
            a31 = fma2(z67, wc1, a31); a31 = fma2(f67, wd1, a31);
            a32 = fma2(z67, wc2, a32); a32 = fma2(f67, wd2, a32);
        }

        ull P0[4] = {a00, a10, a20, a30};
        ull P1[4] = {a01, a11, a21, a31};
        ull P2[4] = {a02, a12, a22, a32};
        #pragma unroll
        for (int qp = 0; qp < 4; ++qp) {
            float l0,h0,l1,h1,l2,h2;
            upk2(P0[qp], l0, h0); upk2(P1[qp], l1, h1); upk2(P2[qp], l2, h2);
            float sl = fmaxf(l0,0.f)*wsa + fmaxf(l1,0.f)*wsb + fmaxf(l2,0.f)*wsc;
            float sh = fmaxf(h0,0.f)*wsa + fmaxf(h1,0.f)*wsb + fmaxf(h2,0.f)*wsc;
            #pragma unroll
            for (int o = 16; o; o >>= 1) {
                sl += __shfl_xor_sync(0xffffffffu, sl, o);
                sh += __shfl_xor_sync(0xffffffffu, sh, o);
            }
            if (lane == 0) {
                int q0 = qb + 2*qp;
                float lg0 = sl + bsc, lg1 = sh + bsc;
                if (mrow[q0]   == 0) lg0 = -3.0e38f;
                if (mrow[q0+1] == 0) lg1 = -3.0e38f;
                sLog[q0]   = lg0;
                sLog[q0+1] = lg1;
            }
        }
    }
    __syncthreads();

    float v = -3.4e38f;
    for (int i = tid; i < SS; i += 256) v = fmaxf(v, sLog[i]);
    #pragma unroll
    for (int o = 16; o; o >>= 1) v = fmaxf(v, __shfl_xor_sync(0xffffffffu, v, o));
    if (lane == 0) sRed[warp] = v;
    __syncthreads();
    float gmax = sRed[0];
    #pragma unroll
    for (int w = 1; w < 8; ++w) gmax = fmaxf(gmax, sRed[w]);
    __syncthreads();

    float ls = 0.f;
    for (int i = tid; i < SS; i += 256) {
        float e = expf(sLog[i] - gmax);
        sLog[i] = e;
        ls += e;
    }
    #pragma unroll
    for (int o = 16; o; o >>= 1) ls += __shfl_xor_sync(0xffffffffu, ls, o);
    if (lane == 0) sRed[warp] = ls;
    __syncthreads();
    float gsum = 0.f;
    #pragma unroll
    for (int w = 0; w < 8; ++w) gsum += sRed[w];
    float inv = 1.f / gsum;

    float* prow = g_probs + ((size_t)b*SS + p)*SS;
    for (int i = tid; i < SS; i += 256) prow[i] = sLog[i] * inv;
}

// ---------------- tf32 tensor-core GEMM, 64x64 tile, 256 threads, BK=32 ----------------
// C(MxN) = A(MxK) @ B(KxN), row-major. K-tile 32 (4 ksteps of 8).
// 8 warps as 4(m) x 2(n); warp tile 16x32 = 4 m16n8k8 frags (ni 0..3).
// Smem holds A/B in mma-fragment order; producers write whole lane-fragments:
//   A: thread loads (m,k),(m+8,k),(m,k+4),(m+8,k+4) -> 1 conflict-free STS.128
//   B: thread loads (k,n),(k+4,n)                   -> 1 conflict-free STS.64
// MODE 0: plain; 1: relu(+bias); 2: alpha*(+bias). FUSE: A = [ctx | Hj | ctx*Hj].
template<int MODE, bool FUSE>
__global__ void __launch_bounds__(256) gemm_tf32(
        const float* __restrict__ A, const float* __restrict__ Bm, float* __restrict__ C,
        int K, int N, size_t strA, size_t strB, size_t strC,
        const float* __restrict__ bias, const float* __restrict__ alphap,
        const float* __restrict__ Ctx, const float* __restrict__ HjP)
{
    A  += (size_t)blockIdx.z * strA;
    Bm += (size_t)blockIdx.z * strB;
    C  += (size_t)blockIdx.z * strC;

    // A: 16 frag-tiles (ks*4 + mtile) x 128 words; B: 32 frag-tiles (ks*8 + ntile) x 64 words
    __shared__ __align__(16) unsigned shA[2][2048];
    __shared__ __align__(16) unsigned shB[2][2048];

    int tid = threadIdx.x;
    int lane = tid & 31, warp = tid >> 5;
    int warp_m = warp >> 1, warp_n = warp & 1;
    int blockM = blockIdx.y * 64, blockN = blockIdx.x * 64;

    float acc[4][4];
    #pragma unroll
    for (int ni = 0; ni < 4; ++ni)
        #pragma unroll
        for (int r = 0; r < 4; ++r) acc[ni][r] = 0.f;

    int lm = lane >> 2, lk = lane & 3;       // fragment lane coords

    // ---- A staging: warp handles frag-tiles {warp*2, warp*2+1} of 16 ----
    auto stageA = [&](int kt, float ra[2][4]) {
        #pragma unroll
        for (int i = 0; i < 2; ++i) {
            int at = warp*2 + i;
            int ks = at >> 2, mt = at & 3;
            int m  = blockM + mt*16 + lm;
            int kg = kt + ks*8 + lk;
            if (FUSE) {
                int region = (kg >= 2*HH) ? 2 : ((kg >= HH) ? 1 : 0);
                int kh = kg - region*HH;
                size_t o00 = (size_t)m*HH + kh;
                size_t o10 = o00 + (size_t)8*HH;
                if (region == 0) {
                    ra[i][0] = Ctx[o00];     ra[i][1] = Ctx[o10];
                    ra[i][2] = Ctx[o00 + 4]; ra[i][3] = Ctx[o10 + 4];
                } else if (region == 1) {
                    ra[i][0] = HjP[o00];     ra[i][1] = HjP[o10];
                    ra[i][2] = HjP[o00 + 4]; ra[i][3] = HjP[o10 + 4];
                } else {
                    ra[i][0] = Ctx[o00]     * HjP[o00];
                    ra[i][1] = Ctx[o10]     * HjP[o10];
                    ra[i][2] = Ctx[o00 + 4] * HjP[o00 + 4];
                    ra[i][3] = Ctx[o10 + 4] * HjP[o10 + 4];
                }
            } else {
                const float* p0 = A + (size_t)m*K + kg;
                ra[i][0] = p0[0];
                ra[i][1] = p0[(size_t)8*K];
                ra[i][2] = p0[4];
                ra[i][3] = p0[(size_t)8*K + 4];
            }
        }
    };
    auto commitA = [&](const float ra[2][4], unsigned* dst) {
        #pragma unroll
        for (int i = 0; i < 2; ++i) {
            int at = warp*2 + i;
            uint4 v;
            v.x = cvt_tf32(ra[i][0]); v.y = cvt_tf32(ra[i][1]);
            v.z = cvt_tf32(ra[i][2]); v.w = cvt_tf32(ra[i][3]);
            *(uint4*)&dst[at*128 + lane*4] = v;
        }
    };
    // ---- B staging: warp handles frag-tiles {warp*4 .. warp*4+3} of 32 ----
    auto stageB = [&](int kt, float rb[4][2]) {
        #pragma unroll
        for (int i = 0; i < 4; ++i) {
            int tb = warp*4 + i;
            int ks = tb >> 3, nt = tb & 7;
            int kg = kt + ks*8 + lk;
            int n  = blockN + nt*8 + lm;
            const float* p0 = Bm + (size_t)kg*N + n;
            rb[i][0] = p0[0];
            rb[i][1] = p0[(size_t)4*N];
        }
    };
    auto commitB = [&](const float rb[4][2], unsigned* dst) {
        #pragma unroll
        for (int i = 0; i < 4; ++i) {
            int tb = warp*4 + i;
            uint2 v;
            v.x = cvt_tf32(rb[i][0]); v.y = cvt_tf32(rb[i][1]);
            *(uint2*)&dst[tb*64 + lane*2] = v;
        }
    };

    // prologue: fill buffer 0
    {
        float ra[2][4], rb[4][2];
        stageA(0, ra); stageB(0, rb);
        commitA(ra, shA[0]); commitB(rb, shB[0]);
    }
    __syncthreads();

    int buf = 0;
    for (int kt = 0; kt < K; kt += 32) {
        float ra[2][4], rb[4][2];
        bool more = (kt + 32) < K;
        if (more) { stageA(kt + 32, ra); stageB(kt + 32, rb); }

        #pragma unroll
        for (int ks = 0; ks < 4; ++ks) {
            unsigned afr[4], bfr[4][2];
            *(uint4*)afr = *(const uint4*)&shA[buf][(ks*4 + warp_m)*128 + lane*4];
            #pragma unroll
            for (int ni = 0; ni < 4; ++ni)
                *(uint2*)bfr[ni] = *(const uint2*)&shB[buf][(ks*8 + warp_n*4 + ni)*64 + lane*2];
            #pragma unroll
            for (int ni = 0; ni < 4; ++ni)
                mma1688(acc[ni], afr, bfr[ni]);
        }

        if (more) { commitA(ra, shA[buf^1]); commitB(rb, shB[buf^1]); }
        __syncthreads();
        buf ^= 1;
    }

    // epilogue
    float al = (MODE == 2) ? *alphap : 1.f;
    int r0 = blockM + warp_m*16 + lm;
    #pragma unroll
    for (int ni = 0; ni < 4; ++ni) {
        int c0 = blockN + warp_n*32 + ni*8 + lk*2;
        float b0 = 0.f, b1 = 0.f;
        if (MODE != 0) { float2 bv = *(const float2*)(bias + c0); b0 = bv.x; b1 = bv.y; }
        float v0 = acc[ni][0] + b0, v1 = acc[ni][1] + b1;
        float v2 = acc[ni][2] + b0, v3 = acc[ni][3] + b1;
        if (MODE == 1) {
            v0 = fmaxf(v0, 0.f); v1 = fmaxf(v1, 0.f);
            v2 = fmaxf(v2, 0.f); v3 = fmaxf(v3, 0.f);
        }
        if (MODE == 2) { v0 *= al; v1 *= al; v2 *= al; v3 *= al; }
        float2 lo; lo.x = v0; lo.y = v1;
        float2 hi; hi.x = v2; hi.y = v3;
        *(float2*)&C[(size_t)r0*N + c0]       = lo;
        *(float2*)&C[(size_t)(r0 + 8)*N + c0] = hi;
    }
}

// ---------------- launch ----------------
extern "C" void kernel_launch(void* const* d_in, const int* in_sizes, int n_in,
                              void* d_out, int out_size)
{
    const float* Hj   = (const float*)d_in[0];
    const float* Hi   = (const float*)d_in[1];
    const float* Wpj  = (const float*)d_in[2];
    const float* Wpi  = (const float*)d_in[3];
    const float* Ws1  = (const float*)d_in[4];
    const float* bs1  = (const float*)d_in[5];
    const float* ws2  = (const float*)d_in[6];
    const float* bs2  = (const float*)d_in[7];
    const float* Wv1  = (const float*)d_in[8];
    const float* bv1  = (const float*)d_in[9];
    const float* Wv2  = (const float*)d_in[10];
    const float* bv2  = (const float*)d_in[11];
    const float* alph = (const float*)d_in[12];
    const int*   amask= (const int*)d_in[13];
    float* out = (float*)d_out;

    float *pProbs, *pCtx, *pMhid;
    cudaGetSymbolAddress((void**)&pProbs, g_probs);
    cudaGetSymbolAddress((void**)&pCtx,   g_ctx);
    cudaGetSymbolAddress((void**)&pMhid,  g_mhid);

    // K1: projections
    proj_kernel<<<dim3(RR/8, 2), dim3(24, 8)>>>(Hj, Hi, Wpj, Wpi);

    // K2: pairwise + softmax (fp32-exact)
    const size_t smemPW = (size_t)(2*DD*MM + DD*ZST + SS + MM + DD + 32) * sizeof(float);
    cudaFuncSetAttribute(pairwise_kernel, cudaFuncAttributeMaxDynamicSharedMemorySize, (int)smemPW);
    pairwise_kernel<<<dim3(SS, BB), 256, smemPW>>>(Ws1, bs1, ws2, bs2, amask);

    // K3: ctx = probs @ H_i   (per batch: M=512, K=512, N=768)
    gemm_tf32<0, false><<<dim3(HH/64, SS/64, BB), 256>>>(
        pProbs, Hi, pCtx, SS, HH,
        (size_t)SS*SS, (size_t)SS*HH, (size_t)SS*HH, nullptr, nullptr, nullptr, nullptr);

    // K4: mhid = relu(X @ Wv1 + bv1), X = [ctx|Hj|ctx*Hj] on the fly (M=2048, K=2304, N=768)
    gemm_tf32<1, true><<<dim3(HH/64, RR/64, 1), 256>>>(
        nullptr, Wv1, pMhid, KX, HH, 0, 0, 0, bv1, nullptr, pCtx, Hj);

    // K5: out = alpha * (mhid @ Wv2 + bv2)  (M=2048, K=768, N=768)
    gemm_tf32<2, false><<<dim3(HH/64, RR/64, 1), 256>>>(
        pMhid, Wv2, out, HH, HH, 0, 0, 0, bv2, alph, nullptr, nullptr);
}

// round 8
// speedup vs baseline: 1.6923x; 1.6923x over previous
#include <cuda_runtime.h>
#include <math.h>

#define BB 4
#define SS 512
#define HH 768
#define DD 24
#define MM 96
#define RR (BB*SS)      // 2048
#define KX (3*HH)       // 2304
#define ZST 514         // padded transpose stride

typedef unsigned long long ull;

// ---------------- f32x2 packed helpers (pairwise kernel) ----------------
__device__ __forceinline__ ull pk2(float lo, float hi) {
    ull r; asm("mov.b64 %0, {%1, %2};" : "=l"(r) : "f"(lo), "f"(hi)); return r;
}
__device__ __forceinline__ ull dup2(float x) { return pk2(x, x); }
__device__ __forceinline__ void upk2(ull v, float& lo, float& hi) {
    asm("mov.b64 {%0, %1}, %2;" : "=f"(lo), "=f"(hi) : "l"(v));
}
__device__ __forceinline__ ull fma2(ull a, ull b, ull c) {
    ull d; asm("fma.rn.f32x2 %0, %1, %2, %3;" : "=l"(d) : "l"(a), "l"(b), "l"(c)); return d;
}
__device__ __forceinline__ ull abs2(ull a) { return a & 0x7fffffff7fffffffULL; }

// ---------------- tf32 helpers ----------------
__device__ __forceinline__ unsigned cvt_tf32(float x) {
    unsigned r; asm("cvt.rna.tf32.f32 %0, %1;" : "=r"(r) : "f"(x)); return r;
}
__device__ __forceinline__ void mma1688(float* c, const unsigned* a, const unsigned* b) {
    asm("mma.sync.aligned.m16n8k8.row.col.f32.tf32.tf32.f32 "
        "{%0,%1,%2,%3}, {%4,%5,%6,%7}, {%8,%9}, {%0,%1,%2,%3};"
        : "+f"(c[0]), "+f"(c[1]), "+f"(c[2]), "+f"(c[3])
        : "r"(a[0]), "r"(a[1]), "r"(a[2]), "r"(a[3]), "r"(b[0]), "r"(b[1]));
}

// ---------------- scratch ----------------
__device__ __align__(16) float g_Zj[BB*SS*DD];
__device__ __align__(16) float g_Zi[BB*SS*DD];
__device__ __align__(16) float g_probs[BB*SS*SS];
__device__ __align__(16) float g_ctx[BB*SS*HH];
__device__ __align__(16) float g_mhid[RR*HH];

// ---------------- K1: Z projections ----------------
__global__ void proj_kernel(const float* __restrict__ Hj, const float* __restrict__ Hi,
                            const float* __restrict__ Wpj, const float* __restrict__ Wpi)
{
    int which = blockIdx.y;
    const float* Hsrc = which ? Hi : Hj;
    const float* W    = which ? Wpi : Wpj;
    float* Z          = which ? g_Zi : g_Zj;
    int row = blockIdx.x * 8 + threadIdx.y;
    int col = threadIdx.x;
    const float* h = Hsrc + (size_t)row * HH;
    float acc = 0.f;
    #pragma unroll 8
    for (int k = 0; k < HH; ++k)
        acc = fmaf(h[k], W[k*DD + col], acc);
    Z[row*DD + col] = acc;
}

// ---------------- K2: fused pairwise scores + softmax -> probs (f32x2, fp32-exact) ----------------
__global__ void __launch_bounds__(256) pairwise_kernel(
        const float* __restrict__ Ws1, const float* __restrict__ bs1,
        const float* __restrict__ ws2, const float* __restrict__ bs2p,
        const int*   __restrict__ mask)
{
    extern __shared__ float smem[];
    float2* sPair  = (float2*)smem;
    float*  sZiT   = smem + 2*DD*MM;
    float*  sLog   = sZiT + DD*ZST;
    float*  sBias  = sLog + SS;
    float*  sZj    = sBias + MM;
    float*  sRed   = sZj + DD;

    int b = blockIdx.y, p = blockIdx.x;
    int tid = threadIdx.x;
    int lane = tid & 31, warp = tid >> 5;

    if (tid < DD) sZj[tid] = g_Zj[((size_t)b*SS + p)*DD + tid];
    __syncthreads();

    {
        const float4* src = (const float4*)(g_Zi + (size_t)b*SS*DD);
        for (int i = tid; i < SS*DD/4; i += 256) {
            float4 v = src[i];
            int q = (4*i) / DD, d0 = (4*i) % DD;
            sZiT[(d0+0)*ZST+q] = v.x;
            sZiT[(d0+1)*ZST+q] = v.y;
            sZiT[(d0+2)*ZST+q] = v.z;
            sZiT[(d0+3)*ZST+q] = v.w;
        }
    }
    for (int idx = tid; idx < DD*MM; idx += 256) {
        int d = idx / MM, m = idx - d*MM;
        float w1i = Ws1[(DD   + d)*MM + m];
        float w1h = Ws1[(2*DD + d)*MM + m];
        float w1d = Ws1[(3*DD + d)*MM + m];
        sPair[idx] = make_float2(fmaf(sZj[d], w1h, w1i), w1d);
    }
    if (tid < MM) {
        float acc = bs1[tid];
        #pragma unroll
        for (int d = 0; d < DD; ++d)
            acc = fmaf(sZj[d], Ws1[d*MM + tid], acc);
        sBias[tid] = acc;
    }
    __syncthreads();

    float zj[DD];
    #pragma unroll
    for (int d = 0; d < DD; ++d) zj[d] = sZj[d];

    int m0 = lane, m1 = lane + 32, m2 = lane + 64;
    float wsa = ws2[m0], wsb = ws2[m1], wsc = ws2[m2];
    ull bi0p = dup2(sBias[m0]), bi1p = dup2(sBias[m1]), bi2p = dup2(sBias[m2]);
    const ull NEG1 = dup2(-1.0f);
    float bsc = bs2p[0];
    const int* mrow = mask + b*SS;

    for (int it = 0; it < SS/64; ++it) {
        int qb = it*64 + warp*8;
        ull a00=bi0p,a01=bi1p,a02=bi2p, a10=bi0p,a11=bi1p,a12=bi2p;
        ull a20=bi0p,a21=bi1p,a22=bi2p, a30=bi0p,a31=bi1p,a32=bi2p;

        #pragma unroll
        for (int d = 0; d < DD; ++d) {
            const float2* zr = (const float2*)&sZiT[d*ZST + qb];
            float2 z01f = zr[0], z23f = zr[1], z45f = zr[2], z67f = zr[3];
            ull z01 = pk2(z01f.x, z01f.y);
            ull z23 = pk2(z23f.x, z23f.y);
            ull z45 = pk2(z45f.x, z45f.y);
            ull z67 = pk2(z67f.x, z67f.y);
            ull zjd = dup2(zj[d]);
            ull f01 = abs2(fma2(z01, NEG1, zjd));
            ull f23 = abs2(fma2(z23, NEG1, zjd));
            ull f45 = abs2(fma2(z45, NEG1, zjd));
            ull f67 = abs2(fma2(z67, NEG1, zjd));
            float2 w0 = sPair[d*MM + m0];
            float2 w1 = sPair[d*MM + m1];
            float2 w2 = sPair[d*MM + m2];
            ull wc0 = dup2(w0.x), wd0 = dup2(w0.y);
            ull wc1 = dup2(w1.x), wd1 = dup2(w1.y);
            ull wc2 = dup2(w2.x), wd2 = dup2(w2.y);
            a00 = fma2(z01, wc0, a00); a00 = fma2(f01, wd0, a00);
            a01 = fma2(z01, wc1, a01); a01 = fma2(f01, wd1, a01);
            a02 = fma2(z01, wc2, a02); a02 = fma2(f01, wd2, a02);
            a10 = fma2(z23, wc0, a10); a10 = fma2(f23, wd0, a10);
            a11 = fma2(z23, wc1, a11); a11 = fma2(f23, wd1, a11);
            a12 = fma2(z23, wc2, a12); a12 = fma2(f23, wd2, a12);
            a20 = fma2(z45, wc0, a20); a20 = fma2(f45, wd0, a20);
            a21 = fma2(z45, wc1, a21); a21 = fma2(f45, wd1, a21);
            a22 = fma2(z45, wc2, a22); a22 = fma2(f45, wd2, a22);
            a30 = fma2(z67, wc0, a30); a30 = fma2(f67, wd0, a30);
            a31 = fma2(z67, wc1, a31); a31 = fma2(f67, wd1, a31);
            a32 = fma2(z67, wc2, a32); a32 = fma2(f67, wd2, a32);
        }

        ull P0[4] = {a00, a10, a20, a30};
        ull P1[4] = {a01, a11, a21, a31};
        ull P2[4] = {a02, a12, a22, a32};
        #pragma unroll
        for (int qp = 0; qp < 4; ++qp) {
            float l0,h0,l1,h1,l2,h2;
            upk2(P0[qp], l0, h0); upk2(P1[qp], l1, h1); upk2(P2[qp], l2, h2);
            float sl = fmaxf(l0,0.f)*wsa + fmaxf(l1,0.f)*wsb + fmaxf(l2,0.f)*wsc;
            float sh = fmaxf(h0,0.f)*wsa + fmaxf(h1,0.f)*wsb + fmaxf(h2,0.f)*wsc;
            #pragma unroll
            for (int o = 16; o; o >>= 1) {
                sl += __shfl_xor_sync(0xffffffffu, sl, o);
                sh += __shfl_xor_sync(0xffffffffu, sh, o);
            }
            if (lane == 0) {
                int q0 = qb + 2*qp;
                float lg0 = sl + bsc, lg1 = sh + bsc;
                if (mrow[q0]   == 0) lg0 = -3.0e38f;
                if (mrow[q0+1] == 0) lg1 = -3.0e38f;
                sLog[q0]   = lg0;
                sLog[q0+1] = lg1;
            }
        }
    }
    __syncthreads();

    float v = -3.4e38f;
    for (int i = tid; i < SS; i += 256) v = fmaxf(v, sLog[i]);
    #pragma unroll
    for (int o = 16; o; o >>= 1) v = fmaxf(v, __shfl_xor_sync(0xffffffffu, v, o));
    if (lane == 0) sRed[warp] = v;
    __syncthreads();
    float gmax = sRed[0];
    #pragma unroll
    for (int w = 1; w < 8; ++w) gmax = fmaxf(gmax, sRed[w]);
    __syncthreads();

    float ls = 0.f;
    for (int i = tid; i < SS; i += 256) {
        float e = expf(sLog[i] - gmax);
        sLog[i] = e;
        ls += e;
    }
    #pragma unroll
    for (int o = 16; o; o >>= 1) ls += __shfl_xor_sync(0xffffffffu, ls, o);
    if (lane == 0) sRed[warp] = ls;
    __syncthreads();
    float gsum = 0.f;
    #pragma unroll
    for (int w = 0; w < 8; ++w) gsum += sRed[w];
    float inv = 1.f / gsum;

    float* prow = g_probs + ((size_t)b*SS + p)*SS;
    for (int i = tid; i < SS; i += 256) prow[i] = sLog[i] * inv;
}

// ---------------- tf32 tensor-core GEMM, 64x64 tile, 256 threads, BK=32, in-block split-K ----------------
// 8 warps: wg = warp>>2 picks k-half (ksteps 0-1 vs 2-3); within a wg, 4 warps form
// 2(m) x 2(n) grid of 32x32 warp tiles (R5's proven LDS:MMA ratio: 2 LDS.128 + 4 LDS.64 per 8 MMAs).
// After mainloop, wg1 dumps accumulators to smem (overlaying staging buffers) and wg0 reduces + epilogue.
// MODE 0: plain; 1: relu(+bias); 2: alpha*(+bias). FUSE: A = [ctx | Hj | ctx*Hj].
template<int MODE, bool FUSE>
__global__ void __launch_bounds__(256) gemm_tf32(
        const float* __restrict__ A, const float* __restrict__ Bm, float* __restrict__ C,
        int K, int N, size_t strA, size_t strB, size_t strC,
        const float* __restrict__ bias, const float* __restrict__ alphap,
        const float* __restrict__ Ctx, const float* __restrict__ HjP)
{
    A  += (size_t)blockIdx.z * strA;
    Bm += (size_t)blockIdx.z * strB;
    C  += (size_t)blockIdx.z * strC;

    // 32KB: shA[2][2048] | shB[2][2048]; after mainloop the first 16KB is reused as the reduction buffer
    __shared__ __align__(16) unsigned shMem[8192];
    unsigned (*shA)[2048] = (unsigned(*)[2048])shMem;
    unsigned (*shB)[2048] = (unsigned(*)[2048])(shMem + 4096);
    float* sRedu = (float*)shMem;   // 4096 floats, overlays shA

    int tid = threadIdx.x;
    int lane = tid & 31, warp = tid >> 5;
    int wg = warp >> 2, wsub = warp & 3;
    int warp_m = wsub >> 1, warp_n = wsub & 1;
    int blockM = blockIdx.y * 64, blockN = blockIdx.x * 64;

    float acc[2][4][4];
    #pragma unroll
    for (int mi = 0; mi < 2; ++mi)
        #pragma unroll
        for (int ni = 0; ni < 4; ++ni)
            #pragma unroll
            for (int r = 0; r < 4; ++r) acc[mi][ni][r] = 0.f;

    int lm = lane >> 2, lk = lane & 3;       // fragment lane coords

    // ---- A staging: 16 frag-tiles (ks*4 + mtile) x 128 words; warp handles {warp*2, warp*2+1} ----
    auto stageA = [&](int kt, float ra[2][4]) {
        #pragma unroll
        for (int i = 0; i < 2; ++i) {
            int at = warp*2 + i;
            int ks = at >> 2, mt = at & 3;
            int m  = blockM + mt*16 + lm;
            int kg = kt + ks*8 + lk;
            if (FUSE) {
                int region = (kg >= 2*HH) ? 2 : ((kg >= HH) ? 1 : 0);
                int kh = kg - region*HH;
                size_t o00 = (size_t)m*HH + kh;
                size_t o10 = o00 + (size_t)8*HH;
                if (region == 0) {
                    ra[i][0] = Ctx[o00];     ra[i][1] = Ctx[o10];
                    ra[i][2] = Ctx[o00 + 4]; ra[i][3] = Ctx[o10 + 4];
                } else if (region == 1) {
                    ra[i][0] = HjP[o00];     ra[i][1] = HjP[o10];
                    ra[i][2] = HjP[o00 + 4]; ra[i][3] = HjP[o10 + 4];
                } else {
                    ra[i][0] = Ctx[o00]     * HjP[o00];
                    ra[i][1] = Ctx[o10]     * HjP[o10];
                    ra[i][2] = Ctx[o00 + 4] * HjP[o00 + 4];
                    ra[i][3] = Ctx[o10 + 4] * HjP[o10 + 4];
                }
            } else {
                const float* p0 = A + (size_t)m*K + kg;
                ra[i][0] = p0[0];
                ra[i][1] = p0[(size_t)8*K];
                ra[i][2] = p0[4];
                ra[i][3] = p0[(size_t)8*K + 4];
            }
        }
    };
    auto commitA = [&](const float ra[2][4], unsigned* dst) {
        #pragma unroll
        for (int i = 0; i < 2; ++i) {
            int at = warp*2 + i;
            uint4 v;
            v.x = cvt_tf32(ra[i][0]); v.y = cvt_tf32(ra[i][1]);
            v.z = cvt_tf32(ra[i][2]); v.w = cvt_tf32(ra[i][3]);
            *(uint4*)&dst[at*128 + lane*4] = v;
        }
    };
    // ---- B staging: 32 frag-tiles (ks*8 + ntile) x 64 words; warp handles {warp*4 .. warp*4+3} ----
    auto stageB = [&](int kt, float rb[4][2]) {
        #pragma unroll
        for (int i = 0; i < 4; ++i) {
            int tb = warp*4 + i;
            int ks = tb >> 3, nt = tb & 7;
            int kg = kt + ks*8 + lk;
            int n  = blockN + nt*8 + lm;
            const float* p0 = Bm + (size_t)kg*N + n;
            rb[i][0] = p0[0];
            rb[i][1] = p0[(size_t)4*N];
        }
    };
    auto commitB = [&](const float rb[4][2], unsigned* dst) {
        #pragma unroll
        for (int i = 0; i < 4; ++i) {
            int tb = warp*4 + i;
            uint2 v;
            v.x = cvt_tf32(rb[i][0]); v.y = cvt_tf32(rb[i][1]);
            *(uint2*)&dst[tb*64 + lane*2] = v;
        }
    };

    // prologue: fill buffer 0
    {
        float ra[2][4], rb[4][2];
        stageA(0, ra); stageB(0, rb);
        commitA(ra, shA[0]); commitB(rb, shB[0]);
    }
    __syncthreads();

    int buf = 0;
    for (int kt = 0; kt < K; kt += 32) {
        float ra[2][4], rb[4][2];
        bool more = (kt + 32) < K;
        if (more) { stageA(kt + 32, ra); stageB(kt + 32, rb); }

        // this wg computes its 2 ksteps with 32x32 warp tiles
        #pragma unroll
        for (int ksl = 0; ksl < 2; ++ksl) {
            int ks = wg*2 + ksl;
            unsigned afr[2][4], bfr[4][2];
            #pragma unroll
            for (int mi = 0; mi < 2; ++mi)
                *(uint4*)afr[mi] = *(const uint4*)&shA[buf][(ks*4 + warp_m*2 + mi)*128 + lane*4];
            #pragma unroll
            for (int ni = 0; ni < 4; ++ni)
                *(uint2*)bfr[ni] = *(const uint2*)&shB[buf][(ks*8 + warp_n*4 + ni)*64 + lane*2];
            #pragma unroll
            for (int mi = 0; mi < 2; ++mi)
                #pragma unroll
                for (int ni = 0; ni < 4; ++ni)
                    mma1688(acc[mi][ni], afr[mi], bfr[ni]);
        }

        if (more) { commitA(ra, shA[buf^1]); commitB(rb, shB[buf^1]); }
        __syncthreads();
        buf ^= 1;
    }

    // ---- in-block split-K reduction: wg1 -> smem, wg0 adds ----
    if (wg == 1) {
        #pragma unroll
        for (int mi = 0; mi < 2; ++mi)
            #pragma unroll
            for (int ni = 0; ni < 4; ++ni) {
                int t = (wsub*2 + mi)*4 + ni;
                *(float4*)&sRedu[t*128 + lane*4] = *(const float4*)acc[mi][ni];
            }
    }
    __syncthreads();
    if (wg == 0) {
        float al = (MODE == 2) ? *alphap : 1.f;
        #pragma unroll
        for (int mi = 0; mi < 2; ++mi) {
            int r0 = blockM + warp_m*32 + mi*16 + lm;
            #pragma unroll
            for (int ni = 0; ni < 4; ++ni) {
                int t = (wsub*2 + mi)*4 + ni;
                float4 part = *(const float4*)&sRedu[t*128 + lane*4];
                int c0 = blockN + warp_n*32 + ni*8 + lk*2;
                float b0 = 0.f, b1 = 0.f;
                if (MODE != 0) { float2 bv = *(const float2*)(bias + c0); b0 = bv.x; b1 = bv.y; }
                float v0 = acc[mi][ni][0] + part.x + b0;
                float v1 = acc[mi][ni][1] + part.y + b1;
                float v2 = acc[mi][ni][2] + part.z + b0;
                float v3 = acc[mi][ni][3] + part.w + b1;
                if (MODE == 1) {
                    v0 = fmaxf(v0, 0.f); v1 = fmaxf(v1, 0.f);
                    v2 = fmaxf(v2, 0.f); v3 = fmaxf(v3, 0.f);
                }
                if (MODE == 2) { v0 *= al; v1 *= al; v2 *= al; v3 *= al; }
                float2 lo; lo.x = v0; lo.y = v1;
                float2 hi; hi.x = v2; hi.y = v3;
                *(float2*)&C[(size_t)r0*N + c0]       = lo;
                *(float2*)&C[(size_t)(r0 + 8)*N + c0] = hi;
            }
        }
    }
}

// ---------------- launch ----------------
extern "C" void kernel_launch(void* const* d_in, const int* in_sizes, int n_in,
                              void* d_out, int out_size)
{
    const float* Hj   = (const float*)d_in[0];
    const float* Hi   = (const float*)d_in[1];
    const float* Wpj  = (const float*)d_in[2];
    const float* Wpi  = (const float*)d_in[3];
    const float* Ws1  = (const float*)d_in[4];
    const float* bs1  = (const float*)d_in[5];
    const float* ws2  = (const float*)d_in[6];
    const float* bs2  = (const float*)d_in[7];
    const float* Wv1  = (const float*)d_in[8];
    const float* bv1  = (const float*)d_in[9];
    const float* Wv2  = (const float*)d_in[10];
    const float* bv2  = (const float*)d_in[11];
    const float* alph = (const float*)d_in[12];
    const int*   amask= (const int*)d_in[13];
    float* out = (float*)d_out;

    float *pProbs, *pCtx, *pMhid;
    cudaGetSymbolAddress((void**)&pProbs, g_probs);
    cudaGetSymbolAddress((void**)&pCtx,   g_ctx);
    cudaGetSymbolAddress((void**)&pMhid,  g_mhid);

    // K1: projections
    proj_kernel<<<dim3(RR/8, 2), dim3(24, 8)>>>(Hj, Hi, Wpj, Wpi);

    // K2: pairwise + softmax (fp32-exact)
    const size_t smemPW = (size_t)(2*DD*MM + DD*ZST + SS + MM + DD + 32) * sizeof(float);
    cudaFuncSetAttribute(pairwise_kernel, cudaFuncAttributeMaxDynamicSharedMemorySize, (int)smemPW);
    pairwise_kernel<<<dim3(SS, BB), 256, smemPW>>>(Ws1, bs1, ws2, bs2, amask);

    // K3: ctx = probs @ H_i   (per batch: M=512, K=512, N=768)
    gemm_tf32<0, false><<<dim3(HH/64, SS/64, BB), 256>>>(
        pProbs, Hi, pCtx, SS, HH,
        (size_t)SS*SS, (size_t)SS*HH, (size_t)SS*HH, nullptr, nullptr, nullptr, nullptr);

    // K4: mhid = relu(X @ Wv1 + bv1), X = [ctx|Hj|ctx*Hj] on the fly (M=2048, K=2304, N=768)
    gemm_tf32<1, true><<<dim3(HH/64, RR/64, 1), 256>>>(
        nullptr, Wv1, pMhid, KX, HH, 0, 0, 0, bv1, nullptr, pCtx, Hj);

    // K5: out = alpha * (mhid @ Wv2 + bv2)  (M=2048, K=768, N=768)
    gemm_tf32<2, false><<<dim3(HH/64, RR/64, 1), 256>>>(
        pMhid, Wv2, out, HH, HH, 0, 0, 0, bv2, alph, nullptr, nullptr);
}